// round 17
// baseline (speedup 1.0000x reference)
#include <cuda_runtime.h>
#include <cuda_bf16.h>
#include <cuda_fp16.h>
#include <cstdint>

// ---------------------------------------------------------------------------
// Problem constants
// ---------------------------------------------------------------------------
#define BB 4
#define CC 2048
#define EE 1024
#define HH 16
#define DD 64
#define MM (BB * CC)          // 8192 rows
#define FF (4 * EE)           // 4096 mlp hidden
#define QKVS 3072             // fused Q|K|V row stride

// Q scale: 1/sqrt(D) * log2(e) folded in, so softmax can use exp2 directly.
#define QSCALE 0.18033688011112042f   // 0.125 * 1.4426950408889634

// ---------------------------------------------------------------------------
// Scratch
// ---------------------------------------------------------------------------
#define MB (1ull << 20)
__device__ __align__(256) unsigned char g_scratch[364 * MB];

#define OFF_N     (0 * MB)      // normed fp16 [MM, EE]
#define OFF_H     (32 * MB)     // h fp16 [MM, EE]
#define OFF_QKV   (64 * MB)     // [MM, 3072] fp16: Q 0-1023, K 1024-2047, V 2048-3071
#define OFF_OUTB  (160 * MB)
#define OFF_M1    (192 * MB)    // m1 fp16 [MM, FF]
#define OFF_WQKV  (320 * MB)    // [3072, 1024] fp16 (6MB)
#define OFF_W1    (332 * MB)
#define OFF_W2    (348 * MB)

// ---------------------------------------------------------------------------
// PTX helpers (baseline compute_103 only — no 'a' features)
// ---------------------------------------------------------------------------
__device__ __forceinline__ uint32_t smem_u32(const void* p) {
    uint32_t a;
    asm("{ .reg .u64 t; cvta.to.shared.u64 t, %1; cvt.u32.u64 %0, t; }"
        : "=r"(a) : "l"(p));
    return a;
}
__device__ __forceinline__ void cpa16(uint32_t d, const void* s) {
    asm volatile("cp.async.cg.shared.global [%0], [%1], 16;" :: "r"(d), "l"(s));
}
#define CP_COMMIT() asm volatile("cp.async.commit_group;" ::: "memory")

__device__ __forceinline__ void ldsm4(uint32_t* r, uint32_t addr) {
    asm volatile("ldmatrix.sync.aligned.m8n8.x4.shared.b16 {%0,%1,%2,%3}, [%4];"
                 : "=r"(r[0]), "=r"(r[1]), "=r"(r[2]), "=r"(r[3]) : "r"(addr));
}
__device__ __forceinline__ void ldsm4t(uint32_t* r, uint32_t addr) {
    asm volatile("ldmatrix.sync.aligned.m8n8.x4.trans.shared.b16 {%0,%1,%2,%3}, [%4];"
                 : "=r"(r[0]), "=r"(r[1]), "=r"(r[2]), "=r"(r[3]) : "r"(addr));
}
__device__ __forceinline__ void mma16816h(float* c, const uint32_t* a,
                                          const uint32_t* b) {
    asm volatile(
        "mma.sync.aligned.m16n8k16.row.col.f32.f16.f16.f32 "
        "{%0,%1,%2,%3}, {%4,%5,%6,%7}, {%8,%9}, {%0,%1,%2,%3};"
        : "+f"(c[0]), "+f"(c[1]), "+f"(c[2]), "+f"(c[3])
        : "r"(a[0]), "r"(a[1]), "r"(a[2]), "r"(a[3]), "r"(b[0]), "r"(b[1]));
}
__device__ __forceinline__ uint32_t pack_h2(float a, float b) {
    __half2 t = __floats2half2_rn(a, b);
    return *reinterpret_cast<uint32_t*>(&t);
}

// ---------------------------------------------------------------------------
// Weight transpose -> fp16:  W[K,N] fp32 -> T[N,K] fp16
// ---------------------------------------------------------------------------
__global__ __launch_bounds__(256) void t16_kernel(
    const float* __restrict__ W, __half* __restrict__ Th, int K, int N)
{
    __shared__ float t[32][33];
    const int n0 = blockIdx.x * 32, k0 = blockIdx.y * 32;
    const int tx = threadIdx.x & 31, ty = threadIdx.x >> 5;
    #pragma unroll
    for (int j = 0; j < 32; j += 8)
        t[ty + j][tx] = W[(size_t)(k0 + ty + j) * N + n0 + tx];
    __syncthreads();
    #pragma unroll
    for (int j = 0; j < 32; j += 8) {
        const float v = t[tx][ty + j];
        Th[(size_t)(n0 + ty + j) * K + k0 + tx] = __float2half_rn(v);
    }
}

// Triple-source: z in {0,1,2} -> (Wz -> Th + z*N*K).  Each W is K x N.
__global__ __launch_bounds__(256) void t16_tri_kernel(
    const float* __restrict__ W0, const float* __restrict__ W1,
    const float* __restrict__ W2, __half* __restrict__ Th, int K, int N)
{
    __shared__ float t[32][33];
    const float* W = (blockIdx.z == 0) ? W0 : (blockIdx.z == 1) ? W1 : W2;
    __half* dst = Th + (size_t)blockIdx.z * N * K;
    const int n0 = blockIdx.x * 32, k0 = blockIdx.y * 32;
    const int tx = threadIdx.x & 31, ty = threadIdx.x >> 5;
    #pragma unroll
    for (int j = 0; j < 32; j += 8)
        t[ty + j][tx] = W[(size_t)(k0 + ty + j) * N + n0 + tx];
    __syncthreads();
    #pragma unroll
    for (int j = 0; j < 32; j += 8) {
        const float v = t[tx][ty + j];
        dst[(size_t)(n0 + ty + j) * K + k0 + tx] = __float2half_rn(v);
    }
}

// ---------------------------------------------------------------------------
// LayerNorm -> fp16, warp-per-row (8 rows/CTA, no __syncthreads)
// ---------------------------------------------------------------------------
__global__ __launch_bounds__(256) void ln16w_kernel(
    const float* __restrict__ x, const float* __restrict__ gamma,
    const float* __restrict__ beta, __half* __restrict__ y)
{
    const int w = threadIdx.x >> 5, lane = threadIdx.x & 31;
    const int row = blockIdx.x * 8 + w;
    const float4* xr = (const float4*)(x + (size_t)row * EE);
    float4 v[8];
    float s = 0.f, s2 = 0.f;
    #pragma unroll
    for (int i = 0; i < 8; i++) {
        v[i] = xr[i * 32 + lane];
        s  += v[i].x + v[i].y + v[i].z + v[i].w;
        s2 += fmaf(v[i].x, v[i].x, fmaf(v[i].y, v[i].y,
              fmaf(v[i].z, v[i].z, v[i].w * v[i].w)));
    }
    #pragma unroll
    for (int o = 16; o > 0; o >>= 1) {
        s  += __shfl_xor_sync(0xffffffffu, s, o);
        s2 += __shfl_xor_sync(0xffffffffu, s2, o);
    }
    const float mean = s * (1.0f / EE);
    const float var  = s2 * (1.0f / EE) - mean * mean;
    const float rstd = rsqrtf(var + 1e-5f);
    uint2* yr = (uint2*)(y + (size_t)row * EE);
    #pragma unroll
    for (int i = 0; i < 8; i++) {
        const int c4 = i * 32 + lane;
        const float4 gv = ((const float4*)gamma)[c4];
        const float4 bv = ((const float4*)beta)[c4];
        const float o0 = (v[i].x - mean) * rstd * gv.x + bv.x;
        const float o1 = (v[i].y - mean) * rstd * gv.y + bv.y;
        const float o2 = (v[i].z - mean) * rstd * gv.z + bv.z;
        const float o3 = (v[i].w - mean) * rstd * gv.w + bv.w;
        yr[c4] = make_uint2(pack_h2(o0, o1), pack_h2(o2, o3));
    }
}

// ---------------------------------------------------------------------------
// fp16 single-pass GEMM: D = A(fp16) @ B(fp16)^T.  128x128 tile,
// K-chunk 64, 3-stage cp.async, single __syncthreads per chunk, 2 CTAs/SM.
// qkv mode (biasK != null): col segments get per-segment bias; seg 0 scaled.
// ---------------------------------------------------------------------------
#define G64ROWB 144u               // 64 halfs + 8 pad = 144B per row
#define G64MAT  18432u             // 128 rows * 144B
#define G64STG  36864u             // A | B
#define GSM1_BYTES (3 * 36864)     // 110592

__global__ __launch_bounds__(256, 2) void gemm_fp16_1p(
    const __half* __restrict__ A, const __half* __restrict__ B,
    const float* __restrict__ bias, const float* __restrict__ biasK,
    const float* __restrict__ biasV,
    const float* __restrict__ res, float* __restrict__ Cf,
    __half* __restrict__ Ch, int M, int N, int K, int relu, float oscale)
{
    extern __shared__ unsigned char smem[];
    const uint32_t sbase = smem_u32(smem);
    const int tid = threadIdx.x;
    const int lane = tid & 31, wid = tid >> 5;
    const int wm = wid >> 2, wn = wid & 3;
    const int row0 = blockIdx.y * 128, col0 = blockIdx.x * 128;

    const __half* gA = A + (size_t)row0 * K;
    const __half* gB = B + (size_t)col0 * K;
    const int nch = K >> 6;              // K-chunk 64

    float acc[4][4][4];
    #pragma unroll
    for (int a = 0; a < 4; a++)
        #pragma unroll
        for (int b = 0; b < 4; b++)
            #pragma unroll
            for (int c = 0; c < 4; c++) acc[a][b][c] = 0.f;

    const uint32_t a_base = (uint32_t)(wm * 64 + (lane & 15)) * G64ROWB +
                            (((lane >> 4) << 3) << 1);
    const uint32_t b_base = (uint32_t)(wn * 32 + ((lane >> 4) << 3) + (lane & 7)) * G64ROWB +
                            ((((lane >> 3) & 1) << 3) << 1);

    auto load_chunk = [&](int ch, int s) {
        const int k0 = ch << 6;
        const uint32_t st = sbase + (uint32_t)s * G64STG;
        #pragma unroll
        for (int i = 0; i < 4; i++) {
            const int idx = i * 256 + tid;
            const int r = idx >> 3, g = idx & 7;
            const uint32_t d = (uint32_t)r * G64ROWB + g * 16u;
            const size_t so = (size_t)r * K + k0 + g * 8;
            cpa16(st + d, gA + so);
            cpa16(st + G64MAT + d, gB + so);
        }
    };

    auto compute_chunk = [&](int s) {
        const uint32_t st = sbase + (uint32_t)s * G64STG;
        #pragma unroll
        for (int ks = 0; ks < 4; ks++) {
            uint32_t aF[4][4], bF[2][4];
            const uint32_t ao = a_base + (ks << 5);
            #pragma unroll
            for (int mi = 0; mi < 4; mi++)
                ldsm4(aF[mi], st + ao + (uint32_t)mi * 16 * G64ROWB);
            const uint32_t bo = b_base + (ks << 5);
            #pragma unroll
            for (int p = 0; p < 2; p++)
                ldsm4(bF[p], st + G64MAT + bo + (uint32_t)p * 16 * G64ROWB);
            #pragma unroll
            for (int mi = 0; mi < 4; mi++)
                #pragma unroll
                for (int p = 0; p < 2; p++)
                    #pragma unroll
                    for (int h = 0; h < 2; h++)
                        mma16816h(acc[mi][p * 2 + h], aF[mi], &bF[p][h * 2]);
        }
    };

    load_chunk(0, 0); CP_COMMIT();
    load_chunk(1, 1); CP_COMMIT();

    for (int ch = 0; ch < nch; ch++) {
        asm volatile("cp.async.wait_group 1;" ::: "memory");
        __syncthreads();
        if (ch + 2 < nch) {
            load_chunk(ch + 2, (ch + 2) % 3);
            CP_COMMIT();
        } else {
            CP_COMMIT();
        }
        compute_chunk(ch % 3);
    }
    asm volatile("cp.async.wait_group 0;" ::: "memory");

    // ---------------- epilogue ----------------
    const float* effb = bias;
    float osc = oscale;
    if (biasK) {                          // fused QKV mode
        if (col0 >= 2048)      { effb = biasV - 2048; osc = 1.0f; }
        else if (col0 >= 1024) { effb = biasK - 1024; osc = 1.0f; }
    }
    const int tr = lane >> 2, tc = (lane & 3) << 1;
    #pragma unroll
    for (int mi = 0; mi < 4; mi++) {
        #pragma unroll
        for (int ni = 0; ni < 4; ni++) {
            const int col = col0 + wn * 32 + ni * 8 + tc;
            const float2 bb = *(const float2*)&effb[col];
            #pragma unroll
            for (int hr = 0; hr < 2; hr++) {
                const int row = row0 + wm * 64 + mi * 16 + tr + hr * 8;
                float v0 = (acc[mi][ni][hr * 2 + 0] + bb.x) * osc;
                float v1 = (acc[mi][ni][hr * 2 + 1] + bb.y) * osc;
                if (relu) { v0 = fmaxf(v0, 0.f); v1 = fmaxf(v1, 0.f); }
                const size_t goff = (size_t)row * N + col;
                if (Cf) {
                    if (res) {
                        const float2 rv = *(const float2*)&res[goff];
                        v0 += rv.x; v1 += rv.y;
                    }
                    *(float2*)&Cf[goff] = make_float2(v0, v1);
                } else {
                    *(uint32_t*)&Ch[goff] = pack_h2(v0, v1);
                }
            }
        }
    }
}

// ---------------------------------------------------------------------------
// Tensor-core flash attention (causal), fp16, exp2 softmax.
// BM=128, BN=128 (KV tile 128 rows), 256 threads (8 warps, warp tile 16x128
// for S, 16x64 for O), 2 CTAs/SM. QKV fused fp16 [M][3072].
// ---------------------------------------------------------------------------
#define AR 144u                   // bytes per smem row (64 fp16 + pad)
#define AQMAT 18432u              // 128 rows * 144B
#define ASTG (2 * AQMAT)          // K(128 rows), V(128 rows) = 36864
#define ATTN_SMEM (AQMAT + 2 * ASTG)   // 92160

__global__ __launch_bounds__(256, 2) void attn_mma(
    const __half* __restrict__ QKV, const float* __restrict__ inp,
    float* __restrict__ Out)
{
    extern __shared__ unsigned char smem[];
    const uint32_t sbase = smem_u32(smem);
    const int tid = threadIdx.x, lane = tid & 31, w = tid >> 5;
    const int qt = gridDim.x - 1 - blockIdx.x;   // longest-first
    const int h = blockIdx.y, b = blockIdx.z;
    const int q0 = qt * 128;
    const int nt = qt + 1;                     // kv tiles (128 rows each)

    // ---- load Q tile (128 rows) ----
    {
        const size_t ro = (size_t)(b * CC + q0) * QKVS + (size_t)h * 64;
        #pragma unroll
        for (int i = 0; i < 4; i++) {
            const int idx = i * 256 + tid;
            const int r = idx >> 3, g = idx & 7;
            cpa16(sbase + (uint32_t)r * AR + g * 16u,
                  QKV + ro + (size_t)r * QKVS + g * 8);
        }
    }
    CP_COMMIT();

    const size_t kvbase = (size_t)(b * CC) * QKVS + 1024 + (size_t)h * 64;
    auto load_kv = [&](int t, int s) {
        const uint32_t st = sbase + AQMAT + (uint32_t)s * ASTG;
        const size_t ro = kvbase + (size_t)(t * 128) * QKVS;
        #pragma unroll
        for (int i = 0; i < 4; i++) {
            const int idx = i * 256 + tid;
            const int r = idx >> 3, g = idx & 7;
            const uint32_t d = st + (uint32_t)r * AR + g * 16u;
            const size_t so = ro + (size_t)r * QKVS + g * 8;
            cpa16(d, QKV + so);                 // K rows 0..127
            cpa16(d + AQMAT, QKV + so + 1024);  // V rows 0..127
        }
    };
    load_kv(0, 0); CP_COMMIT();

    float O[8][4];
    #pragma unroll
    for (int n = 0; n < 8; n++)
        #pragma unroll
        for (int j = 0; j < 4; j++) O[n][j] = 0.f;
    float m_lo = -1e30f, m_hi = -1e30f, l_lo = 0.f, l_hi = 0.f;
    uint32_t qF[4][4];

    const int rowl = w * 16 + (lane >> 2);     // local q row (lo); hi = +8
    const int c0 = (lane & 3) << 1;

    for (int t = 0; t < nt; t++) {
        if (t + 1 < nt) load_kv(t + 1, (t + 1) & 1);
        CP_COMMIT();
        asm volatile("cp.async.wait_group 1;" ::: "memory");
        __syncthreads();

        const uint32_t sK = sbase + AQMAT + (uint32_t)(t & 1) * ASTG;
        const uint32_t sV = sK + AQMAT;

        if (t == 0) {
            const uint32_t qa = sbase + (uint32_t)(w * 16 + (lane & 15)) * AR +
                                (((lane >> 4) << 3) << 1);
            #pragma unroll
            for (int ks = 0; ks < 4; ks++)
                ldsm4(qF[ks], qa + ks * 32);
        }

        // ---- S = Q @ K^T  (16 n-tiles of 8 kv-rows) ----
        float S[16][4];
        #pragma unroll
        for (int n = 0; n < 16; n++)
            #pragma unroll
            for (int j = 0; j < 4; j++) S[n][j] = 0.f;

        #pragma unroll
        for (int ks = 0; ks < 4; ks++) {
            #pragma unroll
            for (int np = 0; np < 8; np += 2) {
                const uint32_t kb0 = sK +
                    (uint32_t)(np * 16 + ((lane >> 4) << 3) + (lane & 7)) * AR +
                    ((((lane >> 3) & 1) << 3) << 1) + ks * 32;
                const uint32_t kb1 = kb0 + 16 * AR;
                uint32_t bh0[4], bh1[4];
                ldsm4(bh0, kb0);
                ldsm4(bh1, kb1);
                #pragma unroll
                for (int h2 = 0; h2 < 2; h2++) {
                    mma16816h(S[np * 2 + h2],       qF[ks], &bh0[h2 * 2]);
                    mma16816h(S[(np + 1) * 2 + h2], qF[ks], &bh1[h2 * 2]);
                }
            }
        }

        // ---- causal mask (diagonal tile only) ----
        if (t == qt) {
            const int colg0 = t * 128;
            const int rg_lo = q0 + rowl, rg_hi = rg_lo + 8;
            #pragma unroll
            for (int n = 0; n < 16; n++) {
                const int col = colg0 + n * 8 + c0;
                if (col > rg_lo)     S[n][0] = -1e30f;
                if (col + 1 > rg_lo) S[n][1] = -1e30f;
                if (col > rg_hi)     S[n][2] = -1e30f;
                if (col + 1 > rg_hi) S[n][3] = -1e30f;
            }
        }

        // ---- online softmax (base-2) ----
        float mx0 = -1e30f, mx1 = -1e30f;
        #pragma unroll
        for (int n = 0; n < 16; n++) {
            mx0 = fmaxf(mx0, fmaxf(S[n][0], S[n][1]));
            mx1 = fmaxf(mx1, fmaxf(S[n][2], S[n][3]));
        }
        mx0 = fmaxf(mx0, __shfl_xor_sync(0xffffffffu, mx0, 1));
        mx0 = fmaxf(mx0, __shfl_xor_sync(0xffffffffu, mx0, 2));
        mx1 = fmaxf(mx1, __shfl_xor_sync(0xffffffffu, mx1, 1));
        mx1 = fmaxf(mx1, __shfl_xor_sync(0xffffffffu, mx1, 2));
        const float mn0 = fmaxf(m_lo, mx0), mn1 = fmaxf(m_hi, mx1);
        const float cr0 = exp2f(m_lo - mn0), cr1 = exp2f(m_hi - mn1);
        float s0 = 0.f, s1 = 0.f;
        #pragma unroll
        for (int n = 0; n < 16; n++) {
            S[n][0] = exp2f(S[n][0] - mn0); s0 += S[n][0];
            S[n][1] = exp2f(S[n][1] - mn0); s0 += S[n][1];
            S[n][2] = exp2f(S[n][2] - mn1); s1 += S[n][2];
            S[n][3] = exp2f(S[n][3] - mn1); s1 += S[n][3];
        }
        s0 += __shfl_xor_sync(0xffffffffu, s0, 1);
        s0 += __shfl_xor_sync(0xffffffffu, s0, 2);
        s1 += __shfl_xor_sync(0xffffffffu, s1, 1);
        s1 += __shfl_xor_sync(0xffffffffu, s1, 2);
        l_lo = l_lo * cr0 + s0; l_hi = l_hi * cr1 + s1;
        m_lo = mn0; m_hi = mn1;
        #pragma unroll
        for (int n = 0; n < 8; n++) {
            O[n][0] *= cr0; O[n][1] *= cr0;
            O[n][2] *= cr1; O[n][3] *= cr1;
        }

        // ---- P -> fp16 A-fragments (8 k16 steps) ----
        uint32_t pF[8][4];
        #pragma unroll
        for (int kk = 0; kk < 8; kk++) {
            pF[kk][0] = pack_h2(S[2 * kk][0],     S[2 * kk][1]);
            pF[kk][1] = pack_h2(S[2 * kk][2],     S[2 * kk][3]);
            pF[kk][2] = pack_h2(S[2 * kk + 1][0], S[2 * kk + 1][1]);
            pF[kk][3] = pack_h2(S[2 * kk + 1][2], S[2 * kk + 1][3]);
        }

        // ---- O += P @ V (ldmatrix.trans for V, 8 k16 steps) ----
        #pragma unroll
        for (int kk = 0; kk < 8; kk++) {
            #pragma unroll
            for (int np = 0; np < 4; np += 2) {
                const uint32_t va0 = sV +
                    (uint32_t)(kk * 16 + ((lane >> 3) & 1) * 8 + (lane & 7)) * AR +
                    ((np * 16 + ((lane >> 4) << 3)) << 1);
                const uint32_t va1 = va0 + 32;
                uint32_t vh0[4], vh1[4];
                ldsm4t(vh0, va0);
                ldsm4t(vh1, va1);
                #pragma unroll
                for (int h2 = 0; h2 < 2; h2++) {
                    mma16816h(O[np * 2 + h2],       pF[kk], &vh0[h2 * 2]);
                    mma16816h(O[(np + 1) * 2 + h2], pF[kk], &vh1[h2 * 2]);
                }
            }
        }
        __syncthreads();
    }

    // ---- finalize ----
    const float inv0 = 1.0f / l_lo, inv1 = 1.0f / l_hi;
    const int gr0 = b * CC + q0 + rowl;
    #pragma unroll
    for (int n = 0; n < 8; n++) {
        const int col = h * 64 + n * 8 + c0;
        const size_t o0 = (size_t)gr0 * EE + col;
        const size_t o1 = o0 + (size_t)8 * EE;
        const float2 i0 = *(const float2*)&inp[o0];
        const float2 i1 = *(const float2*)&inp[o1];
        *(float2*)&Out[o0] = make_float2(i0.x + O[n][0] * inv0,
                                         i0.y + O[n][1] * inv0);
        *(float2*)&Out[o1] = make_float2(i1.x + O[n][2] * inv1,
                                         i1.y + O[n][3] * inv1);
    }
}

// ---------------------------------------------------------------------------
// kernel_launch
// ---------------------------------------------------------------------------
extern "C" void kernel_launch(void* const* d_in, const int* in_sizes, int n_in,
                              void* d_out, int out_size)
{
    const float* inputs = (const float*)d_in[0];
    const float* Wq     = (const float*)d_in[1];
    const float* bq     = (const float*)d_in[2];
    const float* Wk     = (const float*)d_in[3];
    const float* bk     = (const float*)d_in[4];
    const float* Wv     = (const float*)d_in[5];
    const float* bv     = (const float*)d_in[6];
    const float* g1     = (const float*)d_in[7];
    const float* beta1  = (const float*)d_in[8];
    const float* g2     = (const float*)d_in[9];
    const float* beta2  = (const float*)d_in[10];
    const float* W1     = (const float*)d_in[11];
    const float* bm1    = (const float*)d_in[12];
    const float* W2     = (const float*)d_in[13];
    const float* bm2    = (const float*)d_in[14];
    float* out = (float*)d_out;

    unsigned char* base = nullptr;
    cudaGetSymbolAddress((void**)&base, g_scratch);
    __half* nf     = (__half*)(base + OFF_N);
    __half* hf     = (__half*)(base + OFF_H);
    __half* qkvf   = (__half*)(base + OFF_QKV);
    float* outbuf  = (float*)(base + OFF_OUTB);
    __half* m1     = (__half*)(base + OFF_M1);
    __half* WqkvT  = (__half*)(base + OFF_WQKV);
    __half* W1T    = (__half*)(base + OFF_W1);
    __half* W2T    = (__half*)(base + OFF_W2);

    cudaFuncSetAttribute(gemm_fp16_1p, cudaFuncAttributeMaxDynamicSharedMemorySize,
                         GSM1_BYTES);
    cudaFuncSetAttribute(attn_mma, cudaFuncAttributeMaxDynamicSharedMemorySize,
                         ATTN_SMEM);

    // Launch order keeps index 3 == gemm_fp16_1p (fused QKV) for ncu capture.
    // 0: Wq|Wk|Wv prep into fused [3072,1024]
    t16_tri_kernel<<<dim3(EE / 32, EE / 32, 3), 256>>>(Wq, Wk, Wv, WqkvT, EE, EE);
    // 1: LN1 -> fp16 (warp-per-row)
    ln16w_kernel<<<MM / 8, 256>>>(inputs, g1, beta1, nf);
    // 2: W1 prep
    t16_kernel<<<dim3(FF / 32, EE / 32), 256>>>(W1, W1T, EE, FF);
    // 3: fused QKV projection, N=3072, Q scaled by QSCALE (profiled)
    gemm_fp16_1p<<<dim3(QKVS / 128, MM / 128), 256, GSM1_BYTES>>>(
        nf, WqkvT, bq, bk, bv, nullptr, nullptr, qkvf, MM, QKVS, EE, 0, QSCALE);
    // 4: W2 prep
    t16_kernel<<<dim3(EE / 32, FF / 32), 256>>>(W2, W2T, FF, EE);
    // 5: fp16 causal attention + residual (BN=128, exp2 softmax, 2 CTA/SM)
    attn_mma<<<dim3(CC / 128, HH, BB), 256, ATTN_SMEM>>>(qkvf, inputs, outbuf);
    // 6: LN2 -> fp16
    ln16w_kernel<<<MM / 8, 256>>>(outbuf, g2, beta2, hf);
    // 7: MLP1 (relu) -> fp16
    gemm_fp16_1p<<<dim3(FF / 128, MM / 128), 256, GSM1_BYTES>>>(
        hf, W1T, bm1, nullptr, nullptr, nullptr, nullptr, m1, MM, FF, EE, 1, 1.0f);
    // 8: MLP2 + residual -> out
    gemm_fp16_1p<<<dim3(EE / 128, MM / 128), 256, GSM1_BYTES>>>(
        m1, W2T, bm2, nullptr, nullptr, outbuf, out, nullptr, MM, EE, FF, 0, 1.0f);
}